// round 3
// baseline (speedup 1.0000x reference)
#include <cuda_runtime.h>
#include <math.h>

// Problem constants
#define Bb 2
#define Nn 256
#define Dd 256
#define Hh_ 8
#define DHd 32
#define Ee 256
#define SZ_NODES (Bb*Nn*Dd)          // 131072
#define SZ_EDGES ((size_t)Bb*Nn*Nn*Ee) // 33554432
#define M_EDGE   (Bb*Nn*Nn)          // 131072

// ---------------- scratch (static device memory; no runtime allocation) ----------------
__device__ float g_X  [512*256];
__device__ float g_qkv[512*768];
__device__ float g_wv [512*256];
__device__ float g_n1 [512*256];
__device__ float g_nA [512*256];
__device__ float g_nh [512*1024];
__device__ float g_no [512*256];
__device__ float g_R  [(size_t)M_EDGE*256];
__device__ float g_U  [(size_t)M_EDGE*256];
__device__ float g_T  [(size_t)M_EDGE*256];
__device__ float g_Hm [(size_t)M_EDGE*1024];
__device__ float g_O2 [(size_t)M_EDGE*256];

// ---------------- x = nodes + conds (broadcast) ----------------
__global__ void x_kernel(const float* __restrict__ nodes,
                         const float* __restrict__ conds,
                         float* __restrict__ X)
{
    int idx = blockIdx.x * 256 + threadIdx.x;   // 512 blocks * 256
    int b = idx >> 16;          // 65536 elems per batch
    int d = idx & 255;
    X[idx] = nodes[idx] + conds[b * 256 + d];
}

// ---------------- generic SGEMM: C[m,n] = bias[n] + sum_k A[m,k]*W[n,k] ----------------
// A: [M,K] row-major, W: [N,K] row-major ("out,in" layout), C: [M,N].
// Tiles: 128x128x16, 256 threads, 8x8 register tile (split 4+4 for conflict-free smem).
template<bool RELU>
__global__ __launch_bounds__(256, 2)
void sgemm_kernel(const float* __restrict__ A, const float* __restrict__ W,
                  const float* __restrict__ bias, float* __restrict__ C,
                  int M, int N, int K)
{
    __shared__ float As[16][128];
    __shared__ float Ws[16][128];

    const int tid  = threadIdx.x;
    const int tx   = tid & 15;        // 0..15 (col group)
    const int ty   = tid >> 4;        // 0..15 (row group)
    const int lrow = tid >> 2;        // 0..63 (loader row)
    const int lcol = (tid & 3) << 2;  // 0,4,8,12 (loader k offset)

    const float* Ab = A + (size_t)blockIdx.y * 128 * K;
    const float* Wb = W + (size_t)blockIdx.x * 128 * K;

    float acc[8][8];
#pragma unroll
    for (int r = 0; r < 8; r++)
#pragma unroll
        for (int c = 0; c < 8; c++) acc[r][c] = 0.f;

    for (int k0 = 0; k0 < K; k0 += 16) {
        float4 a0 = *(const float4*)(Ab + (size_t)lrow        * K + k0 + lcol);
        float4 a1 = *(const float4*)(Ab + (size_t)(lrow + 64) * K + k0 + lcol);
        float4 w0 = *(const float4*)(Wb + (size_t)lrow        * K + k0 + lcol);
        float4 w1 = *(const float4*)(Wb + (size_t)(lrow + 64) * K + k0 + lcol);
        __syncthreads();   // previous tile's smem reads done
        As[lcol+0][lrow]    = a0.x; As[lcol+1][lrow]    = a0.y;
        As[lcol+2][lrow]    = a0.z; As[lcol+3][lrow]    = a0.w;
        As[lcol+0][lrow+64] = a1.x; As[lcol+1][lrow+64] = a1.y;
        As[lcol+2][lrow+64] = a1.z; As[lcol+3][lrow+64] = a1.w;
        Ws[lcol+0][lrow]    = w0.x; Ws[lcol+1][lrow]    = w0.y;
        Ws[lcol+2][lrow]    = w0.z; Ws[lcol+3][lrow]    = w0.w;
        Ws[lcol+0][lrow+64] = w1.x; Ws[lcol+1][lrow+64] = w1.y;
        Ws[lcol+2][lrow+64] = w1.z; Ws[lcol+3][lrow+64] = w1.w;
        __syncthreads();

#pragma unroll
        for (int kk = 0; kk < 16; kk++) {
            float a[8], w[8];
            *(float4*)(a)     = *(const float4*)&As[kk][ty * 4];
            *(float4*)(a + 4) = *(const float4*)&As[kk][64 + ty * 4];
            *(float4*)(w)     = *(const float4*)&Ws[kk][tx * 4];
            *(float4*)(w + 4) = *(const float4*)&Ws[kk][64 + tx * 4];
#pragma unroll
            for (int r = 0; r < 8; r++)
#pragma unroll
                for (int c = 0; c < 8; c++) acc[r][c] += a[r] * w[c];
        }
    }

    // epilogue: bias (+relu), coalesced float4 stores
    float bv[8];
#pragma unroll
    for (int c = 0; c < 8; c++) {
        int n = blockIdx.x * 128 + ((c < 4) ? (tx * 4 + c) : (64 + tx * 4 + (c - 4)));
        bv[c] = bias[n];
    }
#pragma unroll
    for (int r = 0; r < 8; r++) {
        int row = blockIdx.y * 128 + ((r < 4) ? (ty * 4 + r) : (64 + ty * 4 + (r - 4)));
        float4 o0, o1;
        float v;
        v = acc[r][0] + bv[0]; if (RELU) v = fmaxf(v, 0.f); o0.x = v;
        v = acc[r][1] + bv[1]; if (RELU) v = fmaxf(v, 0.f); o0.y = v;
        v = acc[r][2] + bv[2]; if (RELU) v = fmaxf(v, 0.f); o0.z = v;
        v = acc[r][3] + bv[3]; if (RELU) v = fmaxf(v, 0.f); o0.w = v;
        v = acc[r][4] + bv[4]; if (RELU) v = fmaxf(v, 0.f); o1.x = v;
        v = acc[r][5] + bv[5]; if (RELU) v = fmaxf(v, 0.f); o1.y = v;
        v = acc[r][6] + bv[6]; if (RELU) v = fmaxf(v, 0.f); o1.z = v;
        v = acc[r][7] + bv[7]; if (RELU) v = fmaxf(v, 0.f); o1.w = v;
        float* Crow = C + (size_t)row * N + blockIdx.x * 128;
        *(float4*)(Crow + tx * 4)      = o0;
        *(float4*)(Crow + 64 + tx * 4) = o1;
    }
}

// ---------------- attention: logits -> softmax -> wv, block per (i,h,b) ----------------
__global__ __launch_bounds__(256)
void attn_kernel(const float* __restrict__ qkv, const float* __restrict__ edges,
                 float* __restrict__ wv)
{
    int i = blockIdx.x, h = blockIdx.y, b = blockIdx.z;
    __shared__ __align__(16) float q[32];
    __shared__ float p[256];
    __shared__ float red[256];
    __shared__ float pv[8][32];
    int tid = threadIdx.x;

    if (tid < 32) q[tid] = qkv[((size_t)(b * 256 + i)) * 768 + h * 32 + tid];
    __syncthreads();

    // logit_j = (q . k_j)/16 + sum_d e[b,i,j, h*32+d]
    int j = tid;
    const float4* k4 = (const float4*)(qkv + ((size_t)(b * 256 + j)) * 768 + 256 + h * 32);
    const float4* e4 = (const float4*)(edges + (((size_t)(b * 256 + i)) * 256 + j) * 256 + h * 32);
    float dot = 0.f, es = 0.f;
#pragma unroll
    for (int d4 = 0; d4 < 8; d4++) {
        float4 kv = k4[d4];
        float4 ev = e4[d4];
        float4 qv = *(const float4*)&q[d4 * 4];
        dot += qv.x * kv.x + qv.y * kv.y + qv.z * kv.z + qv.w * kv.w;
        es  += ev.x + ev.y + ev.z + ev.w;
    }
    float logit = dot * 0.0625f + es;

    // softmax over j (256)
    red[tid] = logit; __syncthreads();
    for (int s = 128; s > 0; s >>= 1) {
        if (tid < s) red[tid] = fmaxf(red[tid], red[tid + s]);
        __syncthreads();
    }
    float mx = red[0];
    __syncthreads();
    float e = expf(logit - mx);
    p[tid] = e; red[tid] = e; __syncthreads();
    for (int s = 128; s > 0; s >>= 1) {
        if (tid < s) red[tid] += red[tid + s];
        __syncthreads();
    }
    float inv = 1.f / red[0];

    // wv[d] = inv * sum_j p_j * v[b,j,h,d]
    int d = tid & 31, g = tid >> 5;
    float acc = 0.f;
    for (int jj = g * 32; jj < g * 32 + 32; jj++)
        acc += p[jj] * qkv[((size_t)(b * 256 + jj)) * 768 + 512 + h * 32 + d];
    pv[g][d] = acc;
    __syncthreads();
    if (tid < 32) {
        float s = 0.f;
#pragma unroll
        for (int g2 = 0; g2 < 8; g2++) s += pv[g2][tid];
        wv[((size_t)(b * 256 + i)) * 256 + h * 32 + tid] = s * inv;
    }
}

// ---------------- R[m,:] = q_i (*) k_j / 16 + e_ij  (elementwise over D) ----------------
__global__ __launch_bounds__(256)
void buildR_kernel(const float* __restrict__ qkv, const float* __restrict__ edges,
                   float* __restrict__ R)
{
    size_t idx = (size_t)blockIdx.x * 256 + threadIdx.x;   // float4 index, 8388608 total
    size_t m = idx >> 6;
    int c4 = (int)(idx & 63);
    int b = (int)(m >> 16);
    int i = (int)((m >> 8) & 255);
    int j = (int)(m & 255);
    float4 qv = *(const float4*)(qkv + ((size_t)(b * 256 + i)) * 768 + c4 * 4);
    float4 kv = *(const float4*)(qkv + ((size_t)(b * 256 + j)) * 768 + 256 + c4 * 4);
    float4 ev = *(const float4*)(edges + m * 256 + c4 * 4);
    float4 r;
    r.x = qv.x * kv.x * 0.0625f + ev.x;
    r.y = qv.y * kv.y * 0.0625f + ev.y;
    r.z = qv.z * kv.z * 0.0625f + ev.z;
    r.w = qv.w * kv.w * 0.0625f + ev.w;
    *(float4*)(R + m * 256 + c4 * 4) = r;
}

// ---------------- LayerNorm over 256 with residual: out = LN(x + resid)*g + b ----------------
__global__ __launch_bounds__(256)
void ln_kernel(const float* __restrict__ x, const float* __restrict__ resid,
               const float* __restrict__ g, const float* __restrict__ bb,
               float* __restrict__ out)
{
    __shared__ float s1[256];
    __shared__ float s2[256];
    size_t row = blockIdx.x;
    int t = threadIdx.x;
    float v = x[row * 256 + t] + resid[row * 256 + t];
    s1[t] = v; s2[t] = v * v;
    __syncthreads();
    for (int s = 128; s > 0; s >>= 1) {
        if (t < s) { s1[t] += s1[t + s]; s2[t] += s2[t + s]; }
        __syncthreads();
    }
    float mean = s1[0] * (1.f / 256.f);
    float var  = s2[0] * (1.f / 256.f) - mean * mean;
    float inv  = rsqrtf(var + 1e-5f);
    out[row * 256 + t] = (v - mean) * inv * g[t] + bb[t];
}

__global__ void copy_conds(const float* __restrict__ c, float* __restrict__ o)
{
    int t = threadIdx.x;  // 512 threads
    o[t] = c[t];
}

// ---------------- launch ----------------
extern "C" void kernel_launch(void* const* d_in, const int* in_sizes, int n_in,
                              void* d_out, int out_size)
{
    const float* nodes = (const float*)d_in[0];
    const float* edges = (const float*)d_in[1];
    const float* conds = (const float*)d_in[2];
    const float* Wqkv  = (const float*)d_in[3];
    const float* bqkv  = (const float*)d_in[4];
    const float* Wno   = (const float*)d_in[5];
    const float* bno   = (const float*)d_in[6];
    const float* Weo   = (const float*)d_in[7];
    const float* beo   = (const float*)d_in[8];
    const float* g1n   = (const float*)d_in[9];
    const float* b1n   = (const float*)d_in[10];
    const float* g1e   = (const float*)d_in[11];
    const float* b1e   = (const float*)d_in[12];
    const float* Wn1   = (const float*)d_in[13];
    const float* bn1   = (const float*)d_in[14];
    const float* Wn2   = (const float*)d_in[15];
    const float* bn2   = (const float*)d_in[16];
    const float* We1   = (const float*)d_in[17];
    const float* be1   = (const float*)d_in[18];
    const float* We2   = (const float*)d_in[19];
    const float* be2   = (const float*)d_in[20];
    const float* g2n   = (const float*)d_in[21];
    const float* b2n   = (const float*)d_in[22];
    const float* g2e   = (const float*)d_in[23];
    const float* b2e   = (const float*)d_in[24];

    float *X, *QKV, *WV, *N1, *NA, *NH, *NO, *R, *U, *T, *HM, *O2;
    cudaGetSymbolAddress((void**)&X,  g_X);
    cudaGetSymbolAddress((void**)&QKV,g_qkv);
    cudaGetSymbolAddress((void**)&WV, g_wv);
    cudaGetSymbolAddress((void**)&N1, g_n1);
    cudaGetSymbolAddress((void**)&NA, g_nA);
    cudaGetSymbolAddress((void**)&NH, g_nh);
    cudaGetSymbolAddress((void**)&NO, g_no);
    cudaGetSymbolAddress((void**)&R,  g_R);
    cudaGetSymbolAddress((void**)&U,  g_U);
    cudaGetSymbolAddress((void**)&T,  g_T);
    cudaGetSymbolAddress((void**)&HM, g_Hm);
    cudaGetSymbolAddress((void**)&O2, g_O2);

    float* out_nodes = (float*)d_out;
    float* out_edges = out_nodes + SZ_NODES;
    float* out_conds = out_edges + SZ_EDGES;

    // node/attention path
    x_kernel<<<512, 256>>>(nodes, conds, X);
    sgemm_kernel<false><<<dim3(6, 4),   256>>>(X,  Wqkv, bqkv, QKV, 512, 768, 256);
    attn_kernel<<<dim3(256, 8, 2), 256>>>(QKV, edges, WV);
    sgemm_kernel<false><<<dim3(2, 4),   256>>>(WV, Wno,  bno,  N1,  512, 256, 256);
    ln_kernel<<<512, 256>>>(N1, nodes, g1n, b1n, NA);
    sgemm_kernel<true ><<<dim3(8, 4),   256>>>(NA, Wn1,  bn1,  NH,  512, 1024, 256);
    sgemm_kernel<false><<<dim3(2, 4),   256>>>(NH, Wn2,  bn2,  NO,  512, 256, 1024);
    ln_kernel<<<512, 256>>>(NO, NA, g2n, b2n, out_nodes);

    // edge path (dominant)
    buildR_kernel<<<32768, 256>>>(QKV, edges, R);
    sgemm_kernel<true ><<<dim3(2, 1024), 256>>>(R,  Weo, beo, U,  M_EDGE, 256, 256);
    ln_kernel<<<M_EDGE, 256>>>(U, edges, g1e, b1e, T);
    sgemm_kernel<true ><<<dim3(8, 1024), 256>>>(T,  We1, be1, HM, M_EDGE, 1024, 256);
    sgemm_kernel<false><<<dim3(2, 1024), 256>>>(HM, We2, be2, O2, M_EDGE, 256, 1024);
    ln_kernel<<<M_EDGE, 256>>>(O2, T, g2e, b2e, out_edges);

    copy_conds<<<1, 512>>>(conds, out_conds);
}

// round 5
// speedup vs baseline: 1.5667x; 1.5667x over previous
#include <cuda_runtime.h>
#include <cuda_bf16.h>
#include <math.h>
#include <stdint.h>

// Problem constants
#define Bb 2
#define Nn 256
#define Dd 256
#define Ee 256
#define SZ_NODES (Bb*Nn*Dd)            // 131072
#define SZ_EDGES ((size_t)Bb*Nn*Nn*Ee) // 33554432
#define M_EDGE   (Bb*Nn*Nn)            // 131072

// ======================= helpers =======================
__device__ __forceinline__ uint32_t smem_to_u32(const void* smem_ptr) {
    uint32_t addr;
    asm("{ .reg .u64 tmp; cvta.to.shared.u64 tmp, %1; cvt.u32.u64 %0, tmp; }"
        : "=r"(addr) : "l"(smem_ptr));
    return addr;
}
__device__ __forceinline__ float tf32r(float x) {
    uint32_t u;
    asm("cvt.rna.tf32.f32 %0, %1;" : "=r"(u) : "f"(x));
    return __uint_as_float(u);
}
__device__ __forceinline__ void cp16(uint32_t dst, const void* src) {
    asm volatile("cp.async.cg.shared.global [%0], [%1], 16;" :: "r"(dst), "l"(src));
}
__device__ __forceinline__ void cp_commit() {
    asm volatile("cp.async.commit_group;");
}
template<int NMAX>
__device__ __forceinline__ void cp_wait() {
    asm volatile("cp.async.wait_group %0;" :: "n"(NMAX));
}
__device__ __forceinline__ void mma_tf32(float* d, const uint32_t* a, const uint32_t* b) {
    asm volatile(
        "mma.sync.aligned.m16n8k8.row.col.f32.tf32.tf32.f32 "
        "{%0,%1,%2,%3},{%4,%5,%6,%7},{%8,%9},{%0,%1,%2,%3};"
        : "+f"(d[0]), "+f"(d[1]), "+f"(d[2]), "+f"(d[3])
        : "r"(a[0]), "r"(a[1]), "r"(a[2]), "r"(a[3]), "r"(b[0]), "r"(b[1]));
}

// ======================= scratch (static device memory) =======================
__device__ float g_X  [512*256];
__device__ float g_qkv[512*768];
__device__ float g_wv [512*256];
__device__ float g_n1 [512*256];
__device__ float g_nA [512*256];
__device__ float g_nh [512*1024];
__device__ float g_no [512*256];

__device__ float g_R  [(size_t)M_EDGE*256];   // rounded tf32 (fp32 storage)
__device__ float g_U  [(size_t)M_EDGE*256];   // exact
__device__ float g_T  [(size_t)M_EDGE*256];   // exact
__device__ float g_Tr [(size_t)M_EDGE*256];   // rounded
__device__ float g_Hm [(size_t)M_EDGE*1024];  // rounded
__device__ float g_O2 [(size_t)M_EDGE*256];   // exact
__device__ float g_Weor[256*256];
__device__ float g_We1r[1024*256];
__device__ float g_We2r[256*1024];

// ======================= small kernels =======================
__global__ void x_kernel(const float* __restrict__ nodes,
                         const float* __restrict__ conds,
                         float* __restrict__ X)
{
    int idx = blockIdx.x * 256 + threadIdx.x;
    int b = idx >> 16;
    int d = idx & 255;
    X[idx] = nodes[idx] + conds[b * 256 + d];
}

__global__ void wround_kernel(const float* __restrict__ s, float* __restrict__ d, int n)
{
    int i = blockIdx.x * 256 + threadIdx.x;
    if (i < n) d[i] = tf32r(s[i]);
}

// ---------------- fp32 SGEMM for the (small) node path ----------------
template<bool RELU>
__global__ __launch_bounds__(256, 2)
void sgemm_kernel(const float* __restrict__ A, const float* __restrict__ W,
                  const float* __restrict__ bias, float* __restrict__ C,
                  int M, int N, int K)
{
    __shared__ float As[16][128];
    __shared__ float Ws[16][128];
    const int tid  = threadIdx.x;
    const int tx   = tid & 15;
    const int ty   = tid >> 4;
    const int lrow = tid >> 2;
    const int lcol = (tid & 3) << 2;
    const float* Ab = A + (size_t)blockIdx.y * 128 * K;
    const float* Wb = W + (size_t)blockIdx.x * 128 * K;
    float acc[8][8];
#pragma unroll
    for (int r = 0; r < 8; r++)
#pragma unroll
        for (int c = 0; c < 8; c++) acc[r][c] = 0.f;
    for (int k0 = 0; k0 < K; k0 += 16) {
        float4 a0 = *(const float4*)(Ab + (size_t)lrow        * K + k0 + lcol);
        float4 a1 = *(const float4*)(Ab + (size_t)(lrow + 64) * K + k0 + lcol);
        float4 w0 = *(const float4*)(Wb + (size_t)lrow        * K + k0 + lcol);
        float4 w1 = *(const float4*)(Wb + (size_t)(lrow + 64) * K + k0 + lcol);
        __syncthreads();
        As[lcol+0][lrow]    = a0.x; As[lcol+1][lrow]    = a0.y;
        As[lcol+2][lrow]    = a0.z; As[lcol+3][lrow]    = a0.w;
        As[lcol+0][lrow+64] = a1.x; As[lcol+1][lrow+64] = a1.y;
        As[lcol+2][lrow+64] = a1.z; As[lcol+3][lrow+64] = a1.w;
        Ws[lcol+0][lrow]    = w0.x; Ws[lcol+1][lrow]    = w0.y;
        Ws[lcol+2][lrow]    = w0.z; Ws[lcol+3][lrow]    = w0.w;
        Ws[lcol+0][lrow+64] = w1.x; Ws[lcol+1][lrow+64] = w1.y;
        Ws[lcol+2][lrow+64] = w1.z; Ws[lcol+3][lrow+64] = w1.w;
        __syncthreads();
#pragma unroll
        for (int kk = 0; kk < 16; kk++) {
            float a[8], w[8];
            *(float4*)(a)     = *(const float4*)&As[kk][ty * 4];
            *(float4*)(a + 4) = *(const float4*)&As[kk][64 + ty * 4];
            *(float4*)(w)     = *(const float4*)&Ws[kk][tx * 4];
            *(float4*)(w + 4) = *(const float4*)&Ws[kk][64 + tx * 4];
#pragma unroll
            for (int r = 0; r < 8; r++)
#pragma unroll
                for (int c = 0; c < 8; c++) acc[r][c] += a[r] * w[c];
        }
    }
    float bv[8];
#pragma unroll
    for (int c = 0; c < 8; c++) {
        int n = blockIdx.x * 128 + ((c < 4) ? (tx * 4 + c) : (64 + tx * 4 + (c - 4)));
        bv[c] = bias[n];
    }
#pragma unroll
    for (int r = 0; r < 8; r++) {
        int row = blockIdx.y * 128 + ((r < 4) ? (ty * 4 + r) : (64 + ty * 4 + (r - 4)));
        float4 o0, o1; float v;
        v = acc[r][0] + bv[0]; if (RELU) v = fmaxf(v, 0.f); o0.x = v;
        v = acc[r][1] + bv[1]; if (RELU) v = fmaxf(v, 0.f); o0.y = v;
        v = acc[r][2] + bv[2]; if (RELU) v = fmaxf(v, 0.f); o0.z = v;
        v = acc[r][3] + bv[3]; if (RELU) v = fmaxf(v, 0.f); o0.w = v;
        v = acc[r][4] + bv[4]; if (RELU) v = fmaxf(v, 0.f); o1.x = v;
        v = acc[r][5] + bv[5]; if (RELU) v = fmaxf(v, 0.f); o1.y = v;
        v = acc[r][6] + bv[6]; if (RELU) v = fmaxf(v, 0.f); o1.z = v;
        v = acc[r][7] + bv[7]; if (RELU) v = fmaxf(v, 0.f); o1.w = v;
        float* Crow = C + (size_t)row * N + blockIdx.x * 128;
        *(float4*)(Crow + tx * 4)      = o0;
        *(float4*)(Crow + 64 + tx * 4) = o1;
    }
}

// ---------------- attention ----------------
__global__ __launch_bounds__(256)
void attn_kernel(const float* __restrict__ qkv, const float* __restrict__ edges,
                 float* __restrict__ wv)
{
    int i = blockIdx.x, h = blockIdx.y, b = blockIdx.z;
    __shared__ __align__(16) float q[32];
    __shared__ float p[256];
    __shared__ float red[256];
    __shared__ float pv[8][32];
    int tid = threadIdx.x;
    if (tid < 32) q[tid] = qkv[((size_t)(b * 256 + i)) * 768 + h * 32 + tid];
    __syncthreads();
    int j = tid;
    const float4* k4 = (const float4*)(qkv + ((size_t)(b * 256 + j)) * 768 + 256 + h * 32);
    const float4* e4 = (const float4*)(edges + (((size_t)(b * 256 + i)) * 256 + j) * 256 + h * 32);
    float dot = 0.f, es = 0.f;
#pragma unroll
    for (int d4 = 0; d4 < 8; d4++) {
        float4 kv = k4[d4]; float4 ev = e4[d4];
        float4 qv = *(const float4*)&q[d4 * 4];
        dot += qv.x * kv.x + qv.y * kv.y + qv.z * kv.z + qv.w * kv.w;
        es  += ev.x + ev.y + ev.z + ev.w;
    }
    float logit = dot * 0.0625f + es;
    red[tid] = logit; __syncthreads();
    for (int s = 128; s > 0; s >>= 1) {
        if (tid < s) red[tid] = fmaxf(red[tid], red[tid + s]);
        __syncthreads();
    }
    float mx = red[0];
    __syncthreads();
    float e = expf(logit - mx);
    p[tid] = e; red[tid] = e; __syncthreads();
    for (int s = 128; s > 0; s >>= 1) {
        if (tid < s) red[tid] += red[tid + s];
        __syncthreads();
    }
    float inv = 1.f / red[0];
    int d = tid & 31, g = tid >> 5;
    float acc = 0.f;
    for (int jj = g * 32; jj < g * 32 + 32; jj++)
        acc += p[jj] * qkv[((size_t)(b * 256 + jj)) * 768 + 512 + h * 32 + d];
    pv[g][d] = acc;
    __syncthreads();
    if (tid < 32) {
        float s = 0.f;
#pragma unroll
        for (int g2 = 0; g2 < 8; g2++) s += pv[g2][tid];
        wv[((size_t)(b * 256 + i)) * 256 + h * 32 + tid] = s * inv;
    }
}

// ---------------- R = round_tf32( q (*) k / 16 + e ) ----------------
__global__ __launch_bounds__(256)
void buildR_kernel(const float* __restrict__ qkv, const float* __restrict__ edges,
                   float* __restrict__ R)
{
    size_t idx = (size_t)blockIdx.x * 256 + threadIdx.x;   // float4 index
    size_t m = idx >> 6;
    int c4 = (int)(idx & 63);
    int b = (int)(m >> 16);
    int i = (int)((m >> 8) & 255);
    int j = (int)(m & 255);
    float4 qv = *(const float4*)(qkv + ((size_t)(b * 256 + i)) * 768 + c4 * 4);
    float4 kv = *(const float4*)(qkv + ((size_t)(b * 256 + j)) * 768 + 256 + c4 * 4);
    float4 ev = *(const float4*)(edges + m * 256 + c4 * 4);
    float4 r;
    r.x = tf32r(qv.x * kv.x * 0.0625f + ev.x);
    r.y = tf32r(qv.y * kv.y * 0.0625f + ev.y);
    r.z = tf32r(qv.z * kv.z * 0.0625f + ev.z);
    r.w = tf32r(qv.w * kv.w * 0.0625f + ev.w);
    *(float4*)(R + m * 256 + c4 * 4) = r;
}

// ---------------- LayerNorm (optionally also writes tf32-rounded copy) ----------------
template<bool DUAL>
__global__ __launch_bounds__(256)
void ln_kernel(const float* __restrict__ x, const float* __restrict__ resid,
               const float* __restrict__ g, const float* __restrict__ bb,
               float* __restrict__ out, float* __restrict__ out_r)
{
    __shared__ float s1[256];
    __shared__ float s2[256];
    size_t row = blockIdx.x;
    int t = threadIdx.x;
    float v = x[row * 256 + t] + resid[row * 256 + t];
    s1[t] = v; s2[t] = v * v;
    __syncthreads();
    for (int s = 128; s > 0; s >>= 1) {
        if (t < s) { s1[t] += s1[t + s]; s2[t] += s2[t + s]; }
        __syncthreads();
    }
    float mean = s1[0] * (1.f / 256.f);
    float var  = s2[0] * (1.f / 256.f) - mean * mean;
    float inv  = rsqrtf(var + 1e-5f);
    float o = (v - mean) * inv * g[t] + bb[t];
    out[row * 256 + t] = o;
    if (DUAL) out_r[row * 256 + t] = tf32r(o);
}

__global__ void copy_conds(const float* __restrict__ c, float* __restrict__ o)
{
    o[threadIdx.x] = c[threadIdx.x];
}

// ======================= TF32 mma.sync GEMM =======================
// C[m,n] = bias[n] + sum_k A[m,k]*W[n,k]; A,W pre-rounded to tf32 values.
// CTA tile 128x128, 8 warps (warp tile 32x64), K-chunk 32, 2-stage cp.async.
// smem layout per stage: A[128][32] then W[128][32], 16B-XOR swizzle:
//   byte(r,k) = r*128 + ((k*4) ^ ((r&7)*16))
#define TG_STAGE 32768      // 16KB A + 16KB W
#define TG_SMEM  (2*TG_STAGE)

template<bool RELU, bool ROUND>
__global__ __launch_bounds__(256, 2)
void tf32_gemm(const float* __restrict__ A, const float* __restrict__ W,
               const float* __restrict__ bias, float* __restrict__ C,
               int M, int N, int K)
{
    extern __shared__ char smc[];
    const uint32_t sb = smem_to_u32(smc);
    const int tid  = threadIdx.x;
    const int w    = tid >> 5;
    const int lane = tid & 31;
    const int g    = lane >> 2;
    const int t4   = lane & 3;
    const int wm   = (w >> 1) * 32;     // warp M offset (0,32,64,96)
    const int wn   = (w & 1) * 64;      // warp N offset (0,64)
    const int m0   = blockIdx.y * 128;
    const int n0   = blockIdx.x * 128;

    float acc[2][8][4];
#pragma unroll
    for (int mi = 0; mi < 2; mi++)
#pragma unroll
        for (int ni = 0; ni < 8; ni++)
#pragma unroll
            for (int c = 0; c < 4; c++) acc[mi][ni][c] = 0.f;

    const int NCH = K >> 5;

    // staging: 1024 16B-chunks for A, 1024 for W, 256 threads x 4 each
    const int lm = tid >> 1;                 // not used; loader indices below
    (void)lm;

    auto issue = [&](int ch, int s) {
        const int k0 = ch * 32;
        const uint32_t sA = sb + s * TG_STAGE;
        const uint32_t sW = sA + 16384;
#pragma unroll
        for (int i = 0; i < 4; i++) {
            int c = tid + i * 256;
            int r = c >> 3, kc = (c & 7) * 4;
            uint32_t swz = (uint32_t)((kc * 4) ^ ((r & 7) * 16));
            cp16(sA + r * 128 + swz, A + (size_t)(m0 + r) * K + k0 + kc);
            cp16(sW + r * 128 + swz, W + (size_t)(n0 + r) * K + k0 + kc);
        }
        cp_commit();
    };

    issue(0, 0);
    for (int ch = 0; ch < NCH; ch++) {
        const int s = ch & 1;
        if (ch + 1 < NCH) { issue(ch + 1, s ^ 1); cp_wait<1>(); }
        else              { cp_wait<0>(); }
        __syncthreads();

        const char* As = smc + s * TG_STAGE;
        const char* Ws = As + 16384;
#pragma unroll
        for (int ks = 0; ks < 4; ks++) {
            const int ka = ks * 8 + t4;
            const int kb = ka + 4;
            uint32_t afr[2][4];
#pragma unroll
            for (int mi = 0; mi < 2; mi++) {
                int r0 = wm + mi * 16 + g;
                int r1 = r0 + 8;
                afr[mi][0] = *(const uint32_t*)(As + r0 * 128 + ((ka * 4) ^ ((r0 & 7) * 16)));
                afr[mi][1] = *(const uint32_t*)(As + r1 * 128 + ((ka * 4) ^ ((r1 & 7) * 16)));
                afr[mi][2] = *(const uint32_t*)(As + r0 * 128 + ((kb * 4) ^ ((r0 & 7) * 16)));
                afr[mi][3] = *(const uint32_t*)(As + r1 * 128 + ((kb * 4) ^ ((r1 & 7) * 16)));
            }
#pragma unroll
            for (int ni = 0; ni < 8; ni++) {
                int nr = wn + ni * 8 + g;
                uint32_t bfr[2];
                bfr[0] = *(const uint32_t*)(Ws + nr * 128 + ((ka * 4) ^ ((nr & 7) * 16)));
                bfr[1] = *(const uint32_t*)(Ws + nr * 128 + ((kb * 4) ^ ((nr & 7) * 16)));
                mma_tf32(acc[0][ni], afr[0], bfr);
                mma_tf32(acc[1][ni], afr[1], bfr);
            }
        }
        __syncthreads();
    }

    // epilogue: bias (+relu) (+tf32 round), float2 stores
#pragma unroll
    for (int ni = 0; ni < 8; ni++) {
        int cc = n0 + wn + ni * 8 + t4 * 2;
        float2 bv = *(const float2*)(bias + cc);
#pragma unroll
        for (int mi = 0; mi < 2; mi++) {
            int r0 = m0 + wm + mi * 16 + g;
            float v0 = acc[mi][ni][0] + bv.x;
            float v1 = acc[mi][ni][1] + bv.y;
            float v2 = acc[mi][ni][2] + bv.x;
            float v3 = acc[mi][ni][3] + bv.y;
            if (RELU) {
                v0 = fmaxf(v0, 0.f); v1 = fmaxf(v1, 0.f);
                v2 = fmaxf(v2, 0.f); v3 = fmaxf(v3, 0.f);
            }
            if (ROUND) {
                v0 = tf32r(v0); v1 = tf32r(v1);
                v2 = tf32r(v2); v3 = tf32r(v3);
            }
            *(float2*)(C + (size_t)r0 * N + cc)       = make_float2(v0, v1);
            *(float2*)(C + (size_t)(r0 + 8) * N + cc) = make_float2(v2, v3);
        }
    }
}

// ======================= launch =======================
extern "C" void kernel_launch(void* const* d_in, const int* in_sizes, int n_in,
                              void* d_out, int out_size)
{
    const float* nodes = (const float*)d_in[0];
    const float* edges = (const float*)d_in[1];
    const float* conds = (const float*)d_in[2];
    const float* Wqkv  = (const float*)d_in[3];
    const float* bqkv  = (const float*)d_in[4];
    const float* Wno   = (const float*)d_in[5];
    const float* bno   = (const float*)d_in[6];
    const float* Weo   = (const float*)d_in[7];
    const float* beo   = (const float*)d_in[8];
    const float* g1n   = (const float*)d_in[9];
    const float* b1n   = (const float*)d_in[10];
    const float* g1e   = (const float*)d_in[11];
    const float* b1e   = (const float*)d_in[12];
    const float* Wn1   = (const float*)d_in[13];
    const float* bn1   = (const float*)d_in[14];
    const float* Wn2   = (const float*)d_in[15];
    const float* bn2   = (const float*)d_in[16];
    const float* We1   = (const float*)d_in[17];
    const float* be1   = (const float*)d_in[18];
    const float* We2   = (const float*)d_in[19];
    const float* be2   = (const float*)d_in[20];
    const float* g2n   = (const float*)d_in[21];
    const float* b2n   = (const float*)d_in[22];
    const float* g2e   = (const float*)d_in[23];
    const float* b2e   = (const float*)d_in[24];

    float *X, *QKV, *WV, *N1, *NA, *NH, *NO;
    float *R, *U, *T, *Tr, *HM, *O2, *Weor, *We1r, *We2r;
    cudaGetSymbolAddress((void**)&X,    g_X);
    cudaGetSymbolAddress((void**)&QKV,  g_qkv);
    cudaGetSymbolAddress((void**)&WV,   g_wv);
    cudaGetSymbolAddress((void**)&N1,   g_n1);
    cudaGetSymbolAddress((void**)&NA,   g_nA);
    cudaGetSymbolAddress((void**)&NH,   g_nh);
    cudaGetSymbolAddress((void**)&NO,   g_no);
    cudaGetSymbolAddress((void**)&R,    g_R);
    cudaGetSymbolAddress((void**)&U,    g_U);
    cudaGetSymbolAddress((void**)&T,    g_T);
    cudaGetSymbolAddress((void**)&Tr,   g_Tr);
    cudaGetSymbolAddress((void**)&HM,   g_Hm);
    cudaGetSymbolAddress((void**)&O2,   g_O2);
    cudaGetSymbolAddress((void**)&Weor, g_Weor);
    cudaGetSymbolAddress((void**)&We1r, g_We1r);
    cudaGetSymbolAddress((void**)&We2r, g_We2r);

    float* out_nodes = (float*)d_out;
    float* out_edges = out_nodes + SZ_NODES;
    float* out_conds = out_edges + SZ_EDGES;

    cudaFuncSetAttribute(tf32_gemm<true,  false>, cudaFuncAttributeMaxDynamicSharedMemorySize, TG_SMEM);
    cudaFuncSetAttribute(tf32_gemm<true,  true >, cudaFuncAttributeMaxDynamicSharedMemorySize, TG_SMEM);
    cudaFuncSetAttribute(tf32_gemm<false, false>, cudaFuncAttributeMaxDynamicSharedMemorySize, TG_SMEM);

    // weight rounding (tiny)
    wround_kernel<<<256,  256>>>(Weo, Weor, 256 * 256);
    wround_kernel<<<1024, 256>>>(We1, We1r, 1024 * 256);
    wround_kernel<<<1024, 256>>>(We2, We2r, 256 * 1024);

    // node/attention path (fp32, small)
    x_kernel<<<512, 256>>>(nodes, conds, X);
    sgemm_kernel<false><<<dim3(6, 4),   256>>>(X,  Wqkv, bqkv, QKV, 512, 768, 256);
    attn_kernel<<<dim3(256, 8, 2), 256>>>(QKV, edges, WV);
    sgemm_kernel<false><<<dim3(2, 4),   256>>>(WV, Wno,  bno,  N1,  512, 256, 256);
    ln_kernel<false><<<512, 256>>>(N1, nodes, g1n, b1n, NA, nullptr);
    sgemm_kernel<true ><<<dim3(8, 4),   256>>>(NA, Wn1,  bn1,  NH,  512, 1024, 256);
    sgemm_kernel<false><<<dim3(2, 4),   256>>>(NH, Wn2,  bn2,  NO,  512, 256, 1024);
    ln_kernel<false><<<512, 256>>>(NO, NA, g2n, b2n, out_nodes, nullptr);

    // edge path (tf32 tensor cores, dominant)
    buildR_kernel<<<32768, 256>>>(QKV, edges, R);
    // GEMM1: U = relu(R @ Weo^T + beo) (exact fp32 out)
    tf32_gemm<true, false><<<dim3(2, 1024), 256, TG_SMEM>>>(R, Weor, beo, U, M_EDGE, 256, 256);
    // T = LN(U + edges); write exact + rounded
    ln_kernel<true><<<M_EDGE, 256>>>(U, edges, g1e, b1e, T, Tr);
    // GEMM2: HM = round(relu(Tr @ We1^T + be1))
    tf32_gemm<true, true><<<dim3(8, 1024), 256, TG_SMEM>>>(Tr, We1r, be1, HM, M_EDGE, 1024, 256);
    // GEMM3: O2 = HM @ We2^T + be2 (exact fp32 out)
    tf32_gemm<false, false><<<dim3(2, 1024), 256, TG_SMEM>>>(HM, We2r, be2, O2, M_EDGE, 256, 1024);
    // out_edges = LN(O2 + T)
    ln_kernel<false><<<M_EDGE, 256>>>(O2, T, g2e, b2e, out_edges, nullptr);

    copy_conds<<<1, 512>>>(conds, out_conds);
}

// round 6
// speedup vs baseline: 2.9246x; 1.8668x over previous
#include <cuda_runtime.h>
#include <cuda_bf16.h>
#include <math.h>
#include <stdint.h>

// Problem constants
#define Bb 2
#define Nn 256
#define Dd 256
#define Ee 256
#define SZ_NODES (Bb*Nn*Dd)            // 131072
#define SZ_EDGES ((size_t)Bb*Nn*Nn*Ee) // 33554432
#define M_EDGE   (Bb*Nn*Nn)            // 131072

// ======================= helpers =======================
__device__ __forceinline__ uint32_t smem_to_u32(const void* smem_ptr) {
    uint32_t addr;
    asm("{ .reg .u64 tmp; cvta.to.shared.u64 tmp, %1; cvt.u32.u64 %0, tmp; }"
        : "=r"(addr) : "l"(smem_ptr));
    return addr;
}
__device__ __forceinline__ float tf32r(float x) {
    uint32_t u;
    asm("cvt.rna.tf32.f32 %0, %1;" : "=r"(u) : "f"(x));
    return __uint_as_float(u);
}
__device__ __forceinline__ void cp16(uint32_t dst, const void* src) {
    asm volatile("cp.async.cg.shared.global [%0], [%1], 16;" :: "r"(dst), "l"(src));
}
__device__ __forceinline__ void cp_commit() {
    asm volatile("cp.async.commit_group;");
}
template<int NMAX>
__device__ __forceinline__ void cp_wait() {
    asm volatile("cp.async.wait_group %0;" :: "n"(NMAX));
}
__device__ __forceinline__ void mma_tf32(float* d, const uint32_t* a, const uint32_t* b) {
    asm volatile(
        "mma.sync.aligned.m16n8k8.row.col.f32.tf32.tf32.f32 "
        "{%0,%1,%2,%3},{%4,%5,%6,%7},{%8,%9},{%0,%1,%2,%3};"
        : "+f"(d[0]), "+f"(d[1]), "+f"(d[2]), "+f"(d[3])
        : "r"(a[0]), "r"(a[1]), "r"(a[2]), "r"(a[3]), "r"(b[0]), "r"(b[1]));
}

// ======================= scratch (static device memory) =======================
__device__ float g_X  [512*256];
__device__ float g_qkv[512*768];
__device__ float g_wv [512*256];
__device__ float g_n1 [512*256];
__device__ float g_nA [512*256];
__device__ float g_nh [512*1024];
__device__ float g_no [512*256];

__device__ float g_T  [(size_t)M_EDGE*256];   // exact LN1 output
__device__ float g_Tr [(size_t)M_EDGE*256];   // tf32-rounded copy
__device__ float g_Hm [(size_t)M_EDGE*1024];  // rounded MLP hidden
__device__ float g_Weor[256*256];
__device__ float g_We1r[1024*256];
__device__ float g_We2r[256*1024];

// ======================= small kernels =======================
__global__ void x_kernel(const float* __restrict__ nodes,
                         const float* __restrict__ conds,
                         float* __restrict__ X)
{
    int idx = blockIdx.x * 256 + threadIdx.x;
    int b = idx >> 16;
    int d = idx & 255;
    X[idx] = nodes[idx] + conds[b * 256 + d];
}

__global__ void wround_kernel(const float* __restrict__ s, float* __restrict__ d, int n)
{
    int i = blockIdx.x * 256 + threadIdx.x;
    if (i < n) d[i] = tf32r(s[i]);
}

// ---------------- fp32 SGEMM for the (small) node path ----------------
template<bool RELU>
__global__ __launch_bounds__(256, 2)
void sgemm_kernel(const float* __restrict__ A, const float* __restrict__ W,
                  const float* __restrict__ bias, float* __restrict__ C,
                  int M, int N, int K)
{
    __shared__ float As[16][128];
    __shared__ float Ws[16][128];
    const int tid  = threadIdx.x;
    const int tx   = tid & 15;
    const int ty   = tid >> 4;
    const int lrow = tid >> 2;
    const int lcol = (tid & 3) << 2;
    const float* Ab = A + (size_t)blockIdx.y * 128 * K;
    const float* Wb = W + (size_t)blockIdx.x * 128 * K;
    float acc[8][8];
#pragma unroll
    for (int r = 0; r < 8; r++)
#pragma unroll
        for (int c = 0; c < 8; c++) acc[r][c] = 0.f;
    for (int k0 = 0; k0 < K; k0 += 16) {
        float4 a0 = *(const float4*)(Ab + (size_t)lrow        * K + k0 + lcol);
        float4 a1 = *(const float4*)(Ab + (size_t)(lrow + 64) * K + k0 + lcol);
        float4 w0 = *(const float4*)(Wb + (size_t)lrow        * K + k0 + lcol);
        float4 w1 = *(const float4*)(Wb + (size_t)(lrow + 64) * K + k0 + lcol);
        __syncthreads();
        As[lcol+0][lrow]    = a0.x; As[lcol+1][lrow]    = a0.y;
        As[lcol+2][lrow]    = a0.z; As[lcol+3][lrow]    = a0.w;
        As[lcol+0][lrow+64] = a1.x; As[lcol+1][lrow+64] = a1.y;
        As[lcol+2][lrow+64] = a1.z; As[lcol+3][lrow+64] = a1.w;
        Ws[lcol+0][lrow]    = w0.x; Ws[lcol+1][lrow]    = w0.y;
        Ws[lcol+2][lrow]    = w0.z; Ws[lcol+3][lrow]    = w0.w;
        Ws[lcol+0][lrow+64] = w1.x; Ws[lcol+1][lrow+64] = w1.y;
        Ws[lcol+2][lrow+64] = w1.z; Ws[lcol+3][lrow+64] = w1.w;
        __syncthreads();
#pragma unroll
        for (int kk = 0; kk < 16; kk++) {
            float a[8], wv[8];
            *(float4*)(a)      = *(const float4*)&As[kk][ty * 4];
            *(float4*)(a + 4)  = *(const float4*)&As[kk][64 + ty * 4];
            *(float4*)(wv)     = *(const float4*)&Ws[kk][tx * 4];
            *(float4*)(wv + 4) = *(const float4*)&Ws[kk][64 + tx * 4];
#pragma unroll
            for (int r = 0; r < 8; r++)
#pragma unroll
                for (int c = 0; c < 8; c++) acc[r][c] += a[r] * wv[c];
        }
    }
    float bv[8];
#pragma unroll
    for (int c = 0; c < 8; c++) {
        int n = blockIdx.x * 128 + ((c < 4) ? (tx * 4 + c) : (64 + tx * 4 + (c - 4)));
        bv[c] = bias[n];
    }
#pragma unroll
    for (int r = 0; r < 8; r++) {
        int row = blockIdx.y * 128 + ((r < 4) ? (ty * 4 + r) : (64 + ty * 4 + (r - 4)));
        float4 o0, o1; float v;
        v = acc[r][0] + bv[0]; if (RELU) v = fmaxf(v, 0.f); o0.x = v;
        v = acc[r][1] + bv[1]; if (RELU) v = fmaxf(v, 0.f); o0.y = v;
        v = acc[r][2] + bv[2]; if (RELU) v = fmaxf(v, 0.f); o0.z = v;
        v = acc[r][3] + bv[3]; if (RELU) v = fmaxf(v, 0.f); o0.w = v;
        v = acc[r][4] + bv[4]; if (RELU) v = fmaxf(v, 0.f); o1.x = v;
        v = acc[r][5] + bv[5]; if (RELU) v = fmaxf(v, 0.f); o1.y = v;
        v = acc[r][6] + bv[6]; if (RELU) v = fmaxf(v, 0.f); o1.z = v;
        v = acc[r][7] + bv[7]; if (RELU) v = fmaxf(v, 0.f); o1.w = v;
        float* Crow = C + (size_t)row * N + blockIdx.x * 128;
        *(float4*)(Crow + tx * 4)      = o0;
        *(float4*)(Crow + 64 + tx * 4) = o1;
    }
}

// ---------------- attention ----------------
__global__ __launch_bounds__(256)
void attn_kernel(const float* __restrict__ qkv, const float* __restrict__ edges,
                 float* __restrict__ wv)
{
    int i = blockIdx.x, h = blockIdx.y, b = blockIdx.z;
    __shared__ __align__(16) float q[32];
    __shared__ float p[256];
    __shared__ float red[256];
    __shared__ float pv[8][32];
    int tid = threadIdx.x;
    if (tid < 32) q[tid] = qkv[((size_t)(b * 256 + i)) * 768 + h * 32 + tid];
    __syncthreads();
    int j = tid;
    const float4* k4 = (const float4*)(qkv + ((size_t)(b * 256 + j)) * 768 + 256 + h * 32);
    const float4* e4 = (const float4*)(edges + (((size_t)(b * 256 + i)) * 256 + j) * 256 + h * 32);
    float dot = 0.f, es = 0.f;
#pragma unroll
    for (int d4 = 0; d4 < 8; d4++) {
        float4 kv = k4[d4]; float4 ev = e4[d4];
        float4 qv = *(const float4*)&q[d4 * 4];
        dot += qv.x * kv.x + qv.y * kv.y + qv.z * kv.z + qv.w * kv.w;
        es  += ev.x + ev.y + ev.z + ev.w;
    }
    float logit = dot * 0.0625f + es;
    red[tid] = logit; __syncthreads();
    for (int s = 128; s > 0; s >>= 1) {
        if (tid < s) red[tid] = fmaxf(red[tid], red[tid + s]);
        __syncthreads();
    }
    float mx = red[0];
    __syncthreads();
    float e = expf(logit - mx);
    p[tid] = e; red[tid] = e; __syncthreads();
    for (int s = 128; s > 0; s >>= 1) {
        if (tid < s) red[tid] += red[tid + s];
        __syncthreads();
    }
    float inv = 1.f / red[0];
    int d = tid & 31, g = tid >> 5;
    float acc = 0.f;
    for (int jj = g * 32; jj < g * 32 + 32; jj++)
        acc += p[jj] * qkv[((size_t)(b * 256 + jj)) * 768 + 512 + h * 32 + d];
    pv[g][d] = acc;
    __syncthreads();
    if (tid < 32) {
        float s = 0.f;
#pragma unroll
        for (int g2 = 0; g2 < 8; g2++) s += pv[g2][tid];
        wv[((size_t)(b * 256 + i)) * 256 + h * 32 + tid] = s * inv;
    }
}

// ---------------- LayerNorm (node path only) ----------------
__global__ __launch_bounds__(256)
void ln_kernel(const float* __restrict__ x, const float* __restrict__ resid,
               const float* __restrict__ g, const float* __restrict__ bb,
               float* __restrict__ out)
{
    __shared__ float s1[256];
    __shared__ float s2[256];
    size_t row = blockIdx.x;
    int t = threadIdx.x;
    float v = x[row * 256 + t] + resid[row * 256 + t];
    s1[t] = v; s2[t] = v * v;
    __syncthreads();
    for (int s = 128; s > 0; s >>= 1) {
        if (t < s) { s1[t] += s1[t + s]; s2[t] += s2[t + s]; }
        __syncthreads();
    }
    float mean = s1[0] * (1.f / 256.f);
    float var  = s2[0] * (1.f / 256.f) - mean * mean;
    float inv  = rsqrtf(var + 1e-5f);
    out[row * 256 + t] = (v - mean) * inv * g[t] + bb[t];
}

__global__ void copy_conds(const float* __restrict__ c, float* __restrict__ o)
{
    o[threadIdx.x] = c[threadIdx.x];
}

// ======================= fused TF32 GEMM, CTA tile 128x256, warp tile 64x64 =======================
// EPI 0: out0 = tf32r(relu(acc+bias)), row length NFULL, col offset n0       (GEMM2 -> HM)
// EPI 1: v = relu(acc+bias)+resid; LN -> out0 (fp32 T) + out1 (tf32 Tr)      (GEMM1)
// EPI 2: v = acc+bias+resid;       LN -> out0 (fp32 out_edges)               (GEMM3)
// FUSEA: A computed on the fly: A[m,k] = tf32r(q_i[k]*k_j[k]/16 + edges[m,k])
// smem: [0,1K) bias | [1K,2K) gamma | [2K,3K) beta | [3K,4K) q | stages @4K (48KB each x2)
#define TC_SMEM (4096 + 2*49152)

template<int EPI, bool RELU, bool FUSEA, int KT>
__global__ __launch_bounds__(256)
void tc2_gemm(const float* __restrict__ A, const float* __restrict__ W,
              const float* __restrict__ bias, const float* __restrict__ resid,
              const float* __restrict__ gam, const float* __restrict__ bet,
              float* __restrict__ out0, float* __restrict__ out1,
              int NFULL, const float* __restrict__ qkv)
{
    extern __shared__ char smc[];
    const uint32_t sb = smem_to_u32(smc);
    const int tid  = threadIdx.x;
    const int w    = tid >> 5;
    const int lane = tid & 31;
    const int g    = lane >> 2;
    const int t4   = lane & 3;
    const int wm   = (w >> 2) * 64;      // 0 or 64
    const int wn   = (w & 3) * 64;       // 0,64,128,192
    const int m0   = blockIdx.y * 128;
    const int n0   = blockIdx.x * 256;

    float* bias_s = (float*)(smc);
    float* gam_s  = (float*)(smc + 1024);
    float* bet_s  = (float*)(smc + 2048);
    float* qs     = (float*)(smc + 3072);

    bias_s[tid] = bias[n0 + tid];
    if (EPI != 0) { gam_s[tid] = gam[tid]; bet_s[tid] = bet[tid]; }
    int bq = 0, jb = 0;
    if (FUSEA) {
        bq = m0 >> 16;
        int ib = (m0 >> 8) & 255;
        jb = m0 & 255;
        qs[tid] = qkv[(size_t)(bq * 256 + ib) * 768 + tid];
    }
    __syncthreads();

    float acc[4][8][4];
#pragma unroll
    for (int mi = 0; mi < 4; mi++)
#pragma unroll
        for (int ni = 0; ni < 8; ni++)
#pragma unroll
            for (int c = 0; c < 4; c++) acc[mi][ni][c] = 0.f;

    auto issueW = [&](int ch, int s) {
        const int k0 = ch * 32;
        const uint32_t sW = sb + 4096 + s * 49152 + 16384;
#pragma unroll
        for (int i2 = 0; i2 < 8; i2++) {
            int c = tid + i2 * 256;
            int r = c >> 3, kc = (c & 7) * 4;
            cp16(sW + r * 128 + ((kc * 4) ^ ((r & 7) * 16)),
                 W + (size_t)(n0 + r) * KT + k0 + kc);
        }
    };
    auto issueA = [&](int ch, int s) {
        const int k0 = ch * 32;
        const uint32_t sA = sb + 4096 + s * 49152;
#pragma unroll
        for (int i2 = 0; i2 < 4; i2++) {
            int c = tid + i2 * 256;
            int r = c >> 3, kc = (c & 7) * 4;
            cp16(sA + r * 128 + ((kc * 4) ^ ((r & 7) * 16)),
                 A + (size_t)(m0 + r) * KT + k0 + kc);
        }
    };
    auto fuseA = [&](int ch, int s) {
        const int k0 = ch * 32;
        char* sA = smc + 4096 + s * 49152;
#pragma unroll
        for (int i2 = 0; i2 < 4; i2++) {
            int c = tid + i2 * 256;
            int r = c >> 3, kc = (c & 7) * 4;
            float4 e  = *(const float4*)(A + (size_t)(m0 + r) * 256 + k0 + kc);
            float4 kv = *(const float4*)(qkv + (size_t)(bq * 256 + jb + r) * 768 + 256 + k0 + kc);
            float4 qv = *(const float4*)(qs + k0 + kc);
            float4 v;
            v.x = tf32r(qv.x * kv.x * 0.0625f + e.x);
            v.y = tf32r(qv.y * kv.y * 0.0625f + e.y);
            v.z = tf32r(qv.z * kv.z * 0.0625f + e.z);
            v.w = tf32r(qv.w * kv.w * 0.0625f + e.w);
            *(float4*)(sA + r * 128 + ((kc * 4) ^ ((r & 7) * 16))) = v;
        }
    };

    const int NCH = KT / 32;
    if (!FUSEA) issueA(0, 0);
    issueW(0, 0);
    cp_commit();

    for (int ch = 0; ch < NCH; ch++) {
        const int s = ch & 1;
        if (FUSEA) fuseA(ch, s);
        if (ch + 1 < NCH) {
            if (!FUSEA) issueA(ch + 1, s ^ 1);
            issueW(ch + 1, s ^ 1);
            cp_commit();
            cp_wait<1>();
        } else {
            cp_wait<0>();
        }
        __syncthreads();

        const char* As = smc + 4096 + s * 49152;
        const char* Ws = As + 16384;
#pragma unroll
        for (int ks = 0; ks < 4; ks++) {
            const int ka = ks * 8 + t4;
            const int kb = ka + 4;
            uint32_t afr[4][4];
#pragma unroll
            for (int mi = 0; mi < 4; mi++) {
                int r0 = wm + mi * 16 + g, r1 = r0 + 8;
                afr[mi][0] = *(const uint32_t*)(As + r0 * 128 + ((ka * 4) ^ ((r0 & 7) * 16)));
                afr[mi][1] = *(const uint32_t*)(As + r1 * 128 + ((ka * 4) ^ ((r1 & 7) * 16)));
                afr[mi][2] = *(const uint32_t*)(As + r0 * 128 + ((kb * 4) ^ ((r0 & 7) * 16)));
                afr[mi][3] = *(const uint32_t*)(As + r1 * 128 + ((kb * 4) ^ ((r1 & 7) * 16)));
            }
#pragma unroll
            for (int ni = 0; ni < 8; ni++) {
                int nr = wn + ni * 8 + g;
                uint32_t bfr[2];
                bfr[0] = *(const uint32_t*)(Ws + nr * 128 + ((ka * 4) ^ ((nr & 7) * 16)));
                bfr[1] = *(const uint32_t*)(Ws + nr * 128 + ((kb * 4) ^ ((nr & 7) * 16)));
#pragma unroll
                for (int mi = 0; mi < 4; mi++) mma_tf32(acc[mi][ni], afr[mi], bfr);
            }
        }
        __syncthreads();
    }

    // ---------------- epilogue ----------------
    if (EPI == 0) {
#pragma unroll
        for (int mi = 0; mi < 4; mi++)
#pragma unroll
            for (int h = 0; h < 2; h++) {
                int r = m0 + wm + mi * 16 + g + h * 8;
                float* orow = out0 + (size_t)r * NFULL + n0;
#pragma unroll
                for (int ni = 0; ni < 8; ni++) {
                    int col = wn + ni * 8 + t4 * 2;
                    float v0 = acc[mi][ni][h * 2]     + bias_s[col];
                    float v1 = acc[mi][ni][h * 2 + 1] + bias_s[col + 1];
                    if (RELU) { v0 = fmaxf(v0, 0.f); v1 = fmaxf(v1, 0.f); }
                    *(float2*)(orow + col) = make_float2(tf32r(v0), tf32r(v1));
                }
            }
    } else {
        float* rsum = (float*)(smc + 4096);
        float* rsq  = (float*)(smc + 4096 + 2048);
#pragma unroll
        for (int mi = 0; mi < 4; mi++)
#pragma unroll
            for (int h = 0; h < 2; h++) {
                int rl = wm + mi * 16 + g + h * 8;
                const float* rr = resid + (size_t)(m0 + rl) * 256;
                float s = 0.f, q = 0.f;
#pragma unroll
                for (int ni = 0; ni < 8; ni++) {
                    int col = wn + ni * 8 + t4 * 2;
                    float2 rv = *(const float2*)(rr + col);
                    float v0 = acc[mi][ni][h * 2]     + bias_s[col];
                    float v1 = acc[mi][ni][h * 2 + 1] + bias_s[col + 1];
                    if (RELU) { v0 = fmaxf(v0, 0.f); v1 = fmaxf(v1, 0.f); }
                    v0 += rv.x; v1 += rv.y;
                    s += v0 + v1;
                    q += v0 * v0 + v1 * v1;
                }
                s += __shfl_xor_sync(0xFFFFFFFFu, s, 1);
                s += __shfl_xor_sync(0xFFFFFFFFu, s, 2);
                q += __shfl_xor_sync(0xFFFFFFFFu, q, 1);
                q += __shfl_xor_sync(0xFFFFFFFFu, q, 2);
                if (t4 == 0) {
                    rsum[rl * 4 + (w & 3)] = s;
                    rsq [rl * 4 + (w & 3)] = q;
                }
            }
        __syncthreads();
#pragma unroll
        for (int mi = 0; mi < 4; mi++)
#pragma unroll
            for (int h = 0; h < 2; h++) {
                int rl = wm + mi * 16 + g + h * 8;
                float tot = rsum[rl * 4] + rsum[rl * 4 + 1] + rsum[rl * 4 + 2] + rsum[rl * 4 + 3];
                float tq  = rsq [rl * 4] + rsq [rl * 4 + 1] + rsq [rl * 4 + 2] + rsq [rl * 4 + 3];
                float mean = tot * (1.f / 256.f);
                float var  = tq * (1.f / 256.f) - mean * mean;
                float inv  = rsqrtf(var + 1e-5f);
                const float* rr = resid + (size_t)(m0 + rl) * 256;
                size_t orow = (size_t)(m0 + rl) * 256;
#pragma unroll
                for (int ni = 0; ni < 8; ni++) {
                    int col = wn + ni * 8 + t4 * 2;
                    float2 rv = *(const float2*)(rr + col);
                    float v0 = acc[mi][ni][h * 2]     + bias_s[col];
                    float v1 = acc[mi][ni][h * 2 + 1] + bias_s[col + 1];
                    if (RELU) { v0 = fmaxf(v0, 0.f); v1 = fmaxf(v1, 0.f); }
                    v0 += rv.x; v1 += rv.y;
                    float o0 = (v0 - mean) * inv * gam_s[col]     + bet_s[col];
                    float o1 = (v1 - mean) * inv * gam_s[col + 1] + bet_s[col + 1];
                    *(float2*)(out0 + orow + col) = make_float2(o0, o1);
                    if (EPI == 1)
                        *(float2*)(out1 + orow + col) = make_float2(tf32r(o0), tf32r(o1));
                }
            }
    }
}

// ======================= launch =======================
extern "C" void kernel_launch(void* const* d_in, const int* in_sizes, int n_in,
                              void* d_out, int out_size)
{
    const float* nodes = (const float*)d_in[0];
    const float* edges = (const float*)d_in[1];
    const float* conds = (const float*)d_in[2];
    const float* Wqkv  = (const float*)d_in[3];
    const float* bqkv  = (const float*)d_in[4];
    const float* Wno   = (const float*)d_in[5];
    const float* bno   = (const float*)d_in[6];
    const float* Weo   = (const float*)d_in[7];
    const float* beo   = (const float*)d_in[8];
    const float* g1n   = (const float*)d_in[9];
    const float* b1n   = (const float*)d_in[10];
    const float* g1e   = (const float*)d_in[11];
    const float* b1e   = (const float*)d_in[12];
    const float* Wn1   = (const float*)d_in[13];
    const float* bn1   = (const float*)d_in[14];
    const float* Wn2   = (const float*)d_in[15];
    const float* bn2   = (const float*)d_in[16];
    const float* We1   = (const float*)d_in[17];
    const float* be1   = (const float*)d_in[18];
    const float* We2   = (const float*)d_in[19];
    const float* be2   = (const float*)d_in[20];
    const float* g2n   = (const float*)d_in[21];
    const float* b2n   = (const float*)d_in[22];
    const float* g2e   = (const float*)d_in[23];
    const float* b2e   = (const float*)d_in[24];

    float *X, *QKV, *WV, *N1, *NA, *NH, *NO;
    float *T, *Tr, *HM, *Weor, *We1r, *We2r;
    cudaGetSymbolAddress((void**)&X,    g_X);
    cudaGetSymbolAddress((void**)&QKV,  g_qkv);
    cudaGetSymbolAddress((void**)&WV,   g_wv);
    cudaGetSymbolAddress((void**)&N1,   g_n1);
    cudaGetSymbolAddress((void**)&NA,   g_nA);
    cudaGetSymbolAddress((void**)&NH,   g_nh);
    cudaGetSymbolAddress((void**)&NO,   g_no);
    cudaGetSymbolAddress((void**)&T,    g_T);
    cudaGetSymbolAddress((void**)&Tr,   g_Tr);
    cudaGetSymbolAddress((void**)&HM,   g_Hm);
    cudaGetSymbolAddress((void**)&Weor, g_Weor);
    cudaGetSymbolAddress((void**)&We1r, g_We1r);
    cudaGetSymbolAddress((void**)&We2r, g_We2r);

    float* out_nodes = (float*)d_out;
    float* out_edges = out_nodes + SZ_NODES;
    float* out_conds = out_edges + SZ_EDGES;

    cudaFuncSetAttribute(tc2_gemm<1, true,  true,  256>,
                         cudaFuncAttributeMaxDynamicSharedMemorySize, TC_SMEM);
    cudaFuncSetAttribute(tc2_gemm<0, true,  false, 256>,
                         cudaFuncAttributeMaxDynamicSharedMemorySize, TC_SMEM);
    cudaFuncSetAttribute(tc2_gemm<2, false, false, 1024>,
                         cudaFuncAttributeMaxDynamicSharedMemorySize, TC_SMEM);

    // weight rounding (tiny)
    wround_kernel<<<256,  256>>>(Weo, Weor, 256 * 256);
    wround_kernel<<<1024, 256>>>(We1, We1r, 1024 * 256);
    wround_kernel<<<1024, 256>>>(We2, We2r, 256 * 1024);

    // node/attention path (fp32, small)
    x_kernel<<<512, 256>>>(nodes, conds, X);
    sgemm_kernel<false><<<dim3(6, 4),   256>>>(X,  Wqkv, bqkv, QKV, 512, 768, 256);
    attn_kernel<<<dim3(256, 8, 2), 256>>>(QKV, edges, WV);
    sgemm_kernel<false><<<dim3(2, 4),   256>>>(WV, Wno,  bno,  N1,  512, 256, 256);
    ln_kernel<<<512, 256>>>(N1, nodes, g1n, b1n, NA);
    sgemm_kernel<true ><<<dim3(8, 4),   256>>>(NA, Wn1,  bn1,  NH,  512, 1024, 256);
    sgemm_kernel<false><<<dim3(2, 4),   256>>>(NH, Wn2,  bn2,  NO,  512, 256, 1024);
    ln_kernel<<<512, 256>>>(NO, NA, g2n, b2n, out_nodes);

    // edge path (fused tf32 tensor-core GEMMs)
    // GEMM1: build R in-loader, GEMM vs Weo, relu+bias, +edges, LN1 -> T, Tr
    tc2_gemm<1, true, true, 256><<<dim3(1, 1024), 256, TC_SMEM>>>(
        edges, Weor, beo, edges, g1e, b1e, T, Tr, 256, QKV);
    // GEMM2: HM = tf32r(relu(Tr @ We1^T + be1))
    tc2_gemm<0, true, false, 256><<<dim3(4, 1024), 256, TC_SMEM>>>(
        Tr, We1r, be1, nullptr, nullptr, nullptr, HM, nullptr, 1024, nullptr);
    // GEMM3: out_edges = LN(HM @ We2^T + be2 + T)
    tc2_gemm<2, false, false, 1024><<<dim3(1, 1024), 256, TC_SMEM>>>(
        HM, We2r, be2, T, g2e, b2e, out_edges, nullptr, 256, nullptr);

    copy_conds<<<1, 512>>>(conds, out_conds);
}